// round 1
// baseline (speedup 1.0000x reference)
#include <cuda_runtime.h>

#define NN   100000
#define FIN  256
#define HDIM 128
#define CDIM 64

// Scratch (static device globals — allocation-free per harness rules)
__device__ float g_deg[NN];
__device__ float g_dis[NN];
__device__ float g_hw1[NN * HDIM];   // x @ W1
__device__ float g_agg1[NN * HDIM];  // layer-1 aggregated (pre-relu)
__device__ float g_hw2[NN * CDIM];   // relu(h1) @ W2
__device__ float g_agg2[NN * CDIM];  // final h2 (incl. b2)

__global__ void k_zero_deg() {
    int i = blockIdx.x * blockDim.x + threadIdx.x;
    if (i < NN) g_deg[i] = 0.0f;
}

__global__ void k_count_deg(const int* __restrict__ dst, int E) {
    int e = blockIdx.x * blockDim.x + threadIdx.x;
    if (e < E) atomicAdd(&g_deg[dst[e]], 1.0f);
}

__global__ void k_dis() {
    int i = blockIdx.x * blockDim.x + threadIdx.x;
    if (i < NN) g_dis[i] = rsqrtf(g_deg[i] + 1.0f);
}

// Tiled SGEMM with fused epilogue:
//   Cm   = A@B                    (the per-node transformed features, gathered later by src)
//   Cagg = (A@B)*dis[row]^2 + bias  (self-loop term + bias — initializes the scatter target)
// RELU_A applies relu to A on load (layer-2 consumes relu(agg1)).
template<int BM, int BN, int BK, int TM, int TN, bool RELU_A>
__device__ __forceinline__ void sgemm_body(
    int M, int Nn, int K,
    const float* __restrict__ A, const float* __restrict__ B,
    const float* __restrict__ bias, const float* __restrict__ dis,
    float* __restrict__ Cm, float* __restrict__ Cagg)
{
    constexpr int NT = (BM / TM) * (BN / TN);
    __shared__ float As[BK][BM];
    __shared__ float Bs[BK][BN];
    const int tid  = threadIdx.x;
    const int brow = blockIdx.x * BM;
    const int bcol = blockIdx.y * BN;
    const int tcol = tid % (BN / TN);
    const int trow = tid / (BN / TN);

    float acc[TM][TN];
    #pragma unroll
    for (int i = 0; i < TM; i++)
        #pragma unroll
        for (int j = 0; j < TN; j++) acc[i][j] = 0.0f;

    for (int k0 = 0; k0 < K; k0 += BK) {
        constexpr int KV = BK / 4;
        #pragma unroll
        for (int it = 0; it < (BM * BK / 4) / NT; it++) {
            int idx = tid + it * NT;
            int row = idx / KV;
            int kk  = (idx % KV) * 4;
            float4 v = make_float4(0.f, 0.f, 0.f, 0.f);
            int grow = brow + row;
            if (grow < M) v = *(const float4*)(A + (long long)grow * K + k0 + kk);
            if (RELU_A) {
                v.x = fmaxf(v.x, 0.f); v.y = fmaxf(v.y, 0.f);
                v.z = fmaxf(v.z, 0.f); v.w = fmaxf(v.w, 0.f);
            }
            As[kk + 0][row] = v.x; As[kk + 1][row] = v.y;
            As[kk + 2][row] = v.z; As[kk + 3][row] = v.w;
        }
        constexpr int NV = BN / 4;
        #pragma unroll
        for (int it = 0; it < (BK * BN / 4) / NT; it++) {
            int idx = tid + it * NT;
            int kk  = idx / NV;
            int col = (idx % NV) * 4;
            *(float4*)&Bs[kk][col] =
                *(const float4*)(B + (long long)(k0 + kk) * Nn + bcol + col);
        }
        __syncthreads();
        #pragma unroll
        for (int kk = 0; kk < BK; kk++) {
            float ra[TM], rb[TN];
            #pragma unroll
            for (int i = 0; i < TM; i++) ra[i] = As[kk][trow * TM + i];
            #pragma unroll
            for (int j = 0; j < TN; j++) rb[j] = Bs[kk][tcol * TN + j];
            #pragma unroll
            for (int i = 0; i < TM; i++)
                #pragma unroll
                for (int j = 0; j < TN; j++)
                    acc[i][j] += ra[i] * rb[j];
        }
        __syncthreads();
    }

    #pragma unroll
    for (int i = 0; i < TM; i++) {
        int grow = brow + trow * TM + i;
        if (grow >= M) break;
        float d  = dis[grow];
        float d2 = d * d;
        #pragma unroll
        for (int j = 0; j < TN; j += 4) {
            int gcol = bcol + tcol * TN + j;
            float4 v  = make_float4(acc[i][j], acc[i][j+1], acc[i][j+2], acc[i][j+3]);
            *(float4*)(Cm + (long long)grow * Nn + gcol) = v;
            float4 bb = *(const float4*)(bias + gcol);
            float4 va = make_float4(v.x * d2 + bb.x, v.y * d2 + bb.y,
                                    v.z * d2 + bb.z, v.w * d2 + bb.w);
            *(float4*)(Cagg + (long long)grow * Nn + gcol) = va;
        }
    }
}

__global__ void __launch_bounds__(256)
k_sgemm1(const float* __restrict__ x, const float* __restrict__ W1,
         const float* __restrict__ b1)
{
    sgemm_body<128, 128, 16, 8, 8, false>(NN, HDIM, FIN, x, W1, b1,
                                          g_dis, g_hw1, g_agg1);
}

__global__ void __launch_bounds__(256)
k_sgemm2(const float* __restrict__ W2, const float* __restrict__ b2)
{
    sgemm_body<128, 64, 16, 8, 4, true>(NN, CDIM, HDIM, g_agg1, W2, b2,
                                        g_dis, g_hw2, g_agg2);
}

// Layer-1 message scatter: one warp per edge, float4 per lane (128 floats),
// vector atomics (sm_90+ atomicAdd(float4*)) into the L2-resident agg buffer.
__global__ void k_scatter128(const int* __restrict__ src, const int* __restrict__ dst, int E) {
    int t = blockIdx.x * blockDim.x + threadIdx.x;
    int e = t >> 5, lane = t & 31;
    if (e >= E) return;
    int s = src[e], d = dst[e];
    float c = g_dis[s] * g_dis[d];
    float4 v = ((const float4*)(g_hw1 + (long long)s * HDIM))[lane];
    v.x *= c; v.y *= c; v.z *= c; v.w *= c;
    atomicAdd(((float4*)(g_agg1 + (long long)d * HDIM)) + lane, v);
}

// Layer-2 scatter: 16 lanes per edge (64 floats).
__global__ void k_scatter64(const int* __restrict__ src, const int* __restrict__ dst, int E) {
    int t = blockIdx.x * blockDim.x + threadIdx.x;
    int e = t >> 4, lane = t & 15;
    if (e >= E) return;
    int s = src[e], d = dst[e];
    float c = g_dis[s] * g_dis[d];
    float4 v = ((const float4*)(g_hw2 + (long long)s * CDIM))[lane];
    v.x *= c; v.y *= c; v.z *= c; v.w *= c;
    atomicAdd(((float4*)(g_agg2 + (long long)d * CDIM)) + lane, v);
}

// Edge scoring: warp per edge, dot over 64 floats (float2 per lane) + shfl reduce.
__global__ void k_score(const int* __restrict__ pos, const int* __restrict__ neg,
                        int EPn, int SE, float* __restrict__ out)
{
    int t = blockIdx.x * blockDim.x + threadIdx.x;
    int e = t >> 5, lane = t & 31;
    if (e >= SE) return;
    int i, j;
    if (e < EPn) { j = pos[e];        i = pos[e + EPn]; }
    else         { j = neg[e - EPn];  i = neg[e];       }   // neg[(e-EPn)+EPn]
    float2 a = ((const float2*)(g_agg2 + (long long)i * CDIM))[lane];
    float2 b = ((const float2*)(g_agg2 + (long long)j * CDIM))[lane];
    float s = a.x * b.x + a.y * b.y;
    #pragma unroll
    for (int o = 16; o; o >>= 1) s += __shfl_xor_sync(0xffffffffu, s, o);
    if (lane == 0) out[e] = s;
}

__global__ void k_zero_tail(float* __restrict__ out, int n) {
    int i = blockIdx.x * blockDim.x + threadIdx.x;
    if (i < n) out[i] = 0.0f;
}

extern "C" void kernel_launch(void* const* d_in, const int* in_sizes, int n_in,
                              void* d_out, int out_size)
{
    const float* x   = (const float*)d_in[0];
    // d_in[1] = masked_nodes (unused by the reference output)
    const int*   pos = (const int*)d_in[2];
    const int*   neg = (const int*)d_in[3];
    const int*   ei  = (const int*)d_in[4];
    const float* W1  = (const float*)d_in[5];
    const float* b1  = (const float*)d_in[6];
    const float* W2  = (const float*)d_in[7];
    const float* b2  = (const float*)d_in[8];
    float* out = (float*)d_out;

    const int E   = in_sizes[4] / 2;
    const int EPn = in_sizes[2] / 2;
    const int SE  = 2 * EPn;           // number of scored edges
    const int* src = ei;
    const int* dst = ei + E;

    k_zero_deg <<<(NN + 255) / 256, 256>>>();
    k_count_deg<<<(E + 255) / 256, 256>>>(dst, E);
    k_dis      <<<(NN + 255) / 256, 256>>>();

    k_sgemm1<<<dim3((NN + 127) / 128, 1), 256>>>(x, W1, b1);
    k_scatter128<<<(E * 32 + 255) / 256, 256>>>(src, dst, E);

    k_sgemm2<<<dim3((NN + 127) / 128, 1), 256>>>(W2, b2);
    k_scatter64<<<(E * 16 + 255) / 256, 256>>>(src, dst, E);

    k_score<<<(SE * 32 + 255) / 256, 256>>>(pos, neg, EPn, SE, out);

    int tail = out_size - SE;
    if (tail > 0) k_zero_tail<<<(tail + 255) / 256, 256>>>(out + SE, tail);
}

// round 2
// speedup vs baseline: 1.1149x; 1.1149x over previous
#include <cuda_runtime.h>

#define NN   100000
#define FIN  256
#define HDIM 128
#define CDIM 64

// Scratch (static device globals — allocation-free per harness rules)
__device__ float g_deg[NN];
__device__ float g_dis[NN];
__device__ float g_hw1[NN * HDIM];   // x @ W1           (consumed by scatter gather)
__device__ float g_agg1[NN * HDIM];  // layer-1 aggregate (init = self-loop + bias)
__device__ float g_hw2[NN * CDIM];   // relu(agg1) @ W2
__device__ float g_agg2[NN * CDIM];  // final h2

__device__ __forceinline__ void cp_async16(void* smem, const void* gmem) {
    unsigned s = (unsigned)__cvta_generic_to_shared(smem);
    asm volatile("cp.async.ca.shared.global [%0], [%1], 16;\n" :: "r"(s), "l"(gmem));
}
__device__ __forceinline__ void cp_commit() { asm volatile("cp.async.commit_group;\n"); }
__device__ __forceinline__ void cp_wait0()  { asm volatile("cp.async.wait_group 0;\n" ::: "memory"); }

__global__ void k_zero_deg() {
    int i = blockIdx.x * blockDim.x + threadIdx.x;
    if (i < NN) g_deg[i] = 0.0f;
}

__global__ void k_count_deg(const int* __restrict__ dst, int E) {
    int e = blockIdx.x * blockDim.x + threadIdx.x;
    if (e < E) atomicAdd(&g_deg[dst[e]], 1.0f);
}

__global__ void k_dis() {
    int i = blockIdx.x * blockDim.x + threadIdx.x;
    if (i < NN) g_dis[i] = rsqrtf(g_deg[i] + 1.0f);
}

// Double-buffered tiled SGEMM, fused epilogue:
//   Cm   = A@B                      (message features)
//   Cagg = (A@B)*dis[row]^2 + bias  (self-loop term, initializes scatter target)
// A tile: LDG -> registers -> STS (transposed).  B tile: cp.async direct.
template<int BM, int BN, int BK, int TM, int TN, bool RELU_A>
__device__ __forceinline__ void sgemm_db(
    int M, int Nn, int K,
    const float* __restrict__ A, const float* __restrict__ B,
    const float* __restrict__ bias, const float* __restrict__ dis,
    float* __restrict__ Cm, float* __restrict__ Cagg)
{
    constexpr int NT  = (BM / TM) * (BN / TN);     // threads per block
    constexpr int AIT = (BM * BK / 4) / NT;        // float4 A loads per thread
    constexpr int BIT = (BK * BN / 4) / NT;        // float4 B copies per thread

    __shared__ float As[2][BK][BM];
    __shared__ float Bs[2][BK][BN];

    const int tid  = threadIdx.x;
    const int brow = blockIdx.x * BM;
    const int bcol = blockIdx.y * BN;
    const int tcol = tid % (BN / TN);
    const int trow = tid / (BN / TN);

    float acc[TM][TN];
    #pragma unroll
    for (int i = 0; i < TM; i++)
        #pragma unroll
        for (int j = 0; j < TN; j++) acc[i][j] = 0.0f;

    float4 areg[AIT];
    int arow[AIT], akk[AIT];
    #pragma unroll
    for (int it = 0; it < AIT; it++) {
        int idx = tid + it * NT;
        arow[it] = idx / (BK / 4);
        akk[it]  = (idx % (BK / 4)) * 4;
    }

    auto ldgA = [&](int k0) {
        #pragma unroll
        for (int it = 0; it < AIT; it++) {
            int grow = brow + arow[it];
            float4 v = make_float4(0.f, 0.f, 0.f, 0.f);
            if (grow < M) v = *(const float4*)(A + (long long)grow * K + k0 + akk[it]);
            if (RELU_A) {
                v.x = fmaxf(v.x, 0.f); v.y = fmaxf(v.y, 0.f);
                v.z = fmaxf(v.z, 0.f); v.w = fmaxf(v.w, 0.f);
            }
            areg[it] = v;
        }
    };
    auto stsA = [&](int buf) {
        #pragma unroll
        for (int it = 0; it < AIT; it++) {
            As[buf][akk[it] + 0][arow[it]] = areg[it].x;
            As[buf][akk[it] + 1][arow[it]] = areg[it].y;
            As[buf][akk[it] + 2][arow[it]] = areg[it].z;
            As[buf][akk[it] + 3][arow[it]] = areg[it].w;
        }
    };
    auto cpB = [&](int buf, int k0) {
        #pragma unroll
        for (int it = 0; it < BIT; it++) {
            int idx = (tid + it * NT) * 4;
            int kk  = idx / BN;
            int col = idx % BN;
            cp_async16(&Bs[buf][kk][col],
                       B + (long long)(k0 + kk) * Nn + bcol + col);
        }
        cp_commit();
    };
    auto compute = [&](int buf) {
        #pragma unroll
        for (int kk = 0; kk < BK; kk++) {
            float ra[TM], rb[TN];
            #pragma unroll
            for (int i = 0; i < TM; i++) ra[i] = As[buf][kk][trow * TM + i];
            #pragma unroll
            for (int j = 0; j < TN; j++) rb[j] = Bs[buf][kk][tcol * TN + j];
            #pragma unroll
            for (int i = 0; i < TM; i++)
                #pragma unroll
                for (int j = 0; j < TN; j++)
                    acc[i][j] += ra[i] * rb[j];
        }
    };

    // Prologue: fill buffer 0
    ldgA(0);
    cpB(0, 0);
    stsA(0);
    cp_wait0();
    __syncthreads();

    const int NIT = K / BK;
    for (int it = 1; it < NIT; it++) {
        int cur = (it - 1) & 1, nxt = it & 1;
        ldgA(it * BK);          // global loads for next tile (overlap compute)
        cpB(nxt, it * BK);
        compute(cur);
        stsA(nxt);
        cp_wait0();
        __syncthreads();
    }
    compute((NIT - 1) & 1);

    #pragma unroll
    for (int i = 0; i < TM; i++) {
        int grow = brow + trow * TM + i;
        if (grow >= M) break;
        float d  = dis[grow];
        float d2 = d * d;
        #pragma unroll
        for (int j = 0; j < TN; j += 4) {
            int gcol = bcol + tcol * TN + j;
            float4 v  = make_float4(acc[i][j], acc[i][j+1], acc[i][j+2], acc[i][j+3]);
            *(float4*)(Cm + (long long)grow * Nn + gcol) = v;
            float4 bb = *(const float4*)(bias + gcol);
            float4 va = make_float4(v.x * d2 + bb.x, v.y * d2 + bb.y,
                                    v.z * d2 + bb.z, v.w * d2 + bb.w);
            *(float4*)(Cagg + (long long)grow * Nn + gcol) = va;
        }
    }
}

__global__ void __launch_bounds__(256, 2)
k_sgemm1(const float* __restrict__ x, const float* __restrict__ W1,
         const float* __restrict__ b1)
{
    sgemm_db<128, 128, 16, 8, 8, false>(NN, HDIM, FIN, x, W1, b1,
                                        g_dis, g_hw1, g_agg1);
}

__global__ void __launch_bounds__(256, 2)
k_sgemm2(const float* __restrict__ W2, const float* __restrict__ b2)
{
    sgemm_db<128, 64, 16, 8, 4, true>(NN, CDIM, HDIM, g_agg1, W2, b2,
                                      g_dis, g_hw2, g_agg2);
}

// Layer-1 scatter: warp per edge, float4 per lane (128 floats), vector atomics.
__global__ void k_scatter128(const int* __restrict__ src, const int* __restrict__ dst, int E) {
    int t = blockIdx.x * blockDim.x + threadIdx.x;
    int e = t >> 5, lane = t & 31;
    if (e >= E) return;
    int s = src[e], d = dst[e];
    float c = g_dis[s] * g_dis[d];
    float4 v = ((const float4*)(g_hw1 + (long long)s * HDIM))[lane];
    v.x *= c; v.y *= c; v.z *= c; v.w *= c;
    atomicAdd(((float4*)(g_agg1 + (long long)d * HDIM)) + lane, v);
}

// Layer-2 scatter: 16 lanes per edge (64 floats).
__global__ void k_scatter64(const int* __restrict__ src, const int* __restrict__ dst, int E) {
    int t = blockIdx.x * blockDim.x + threadIdx.x;
    int e = t >> 4, lane = t & 15;
    if (e >= E) return;
    int s = src[e], d = dst[e];
    float c = g_dis[s] * g_dis[d];
    float4 v = ((const float4*)(g_hw2 + (long long)s * CDIM))[lane];
    v.x *= c; v.y *= c; v.z *= c; v.w *= c;
    atomicAdd(((float4*)(g_agg2 + (long long)d * CDIM)) + lane, v);
}

// Edge scoring: 16 lanes per edge, float4 per lane, 4-step shfl reduce.
__global__ void k_score(const int* __restrict__ pos, const int* __restrict__ neg,
                        int EPn, int SE, float* __restrict__ out)
{
    int t = blockIdx.x * blockDim.x + threadIdx.x;
    int e = t >> 4, lane = t & 15;
    if (e >= SE) return;
    int i, j;
    if (e < EPn) { j = pos[e];       i = pos[e + EPn]; }
    else         { j = neg[e - EPn]; i = neg[e];       }
    float4 a = ((const float4*)(g_agg2 + (long long)i * CDIM))[lane];
    float4 b = ((const float4*)(g_agg2 + (long long)j * CDIM))[lane];
    float s = a.x * b.x + a.y * b.y + a.z * b.z + a.w * b.w;
    #pragma unroll
    for (int o = 8; o; o >>= 1) s += __shfl_xor_sync(0xffffffffu, s, o);
    if (lane == 0) out[e] = s;
}

__global__ void k_zero_tail(float* __restrict__ out, int n) {
    int i = blockIdx.x * blockDim.x + threadIdx.x;
    if (i < n) out[i] = 0.0f;
}

extern "C" void kernel_launch(void* const* d_in, const int* in_sizes, int n_in,
                              void* d_out, int out_size)
{
    const float* x   = (const float*)d_in[0];
    // d_in[1] = masked_nodes (unused by the reference output)
    const int*   pos = (const int*)d_in[2];
    const int*   neg = (const int*)d_in[3];
    const int*   ei  = (const int*)d_in[4];
    const float* W1  = (const float*)d_in[5];
    const float* b1  = (const float*)d_in[6];
    const float* W2  = (const float*)d_in[7];
    const float* b2  = (const float*)d_in[8];
    float* out = (float*)d_out;

    const int E   = in_sizes[4] / 2;
    const int EPn = in_sizes[2] / 2;
    const int SE  = 2 * EPn;
    const int* src = ei;
    const int* dst = ei + E;

    k_zero_deg <<<(NN + 255) / 256, 256>>>();
    k_count_deg<<<(E + 255) / 256, 256>>>(dst, E);
    k_dis      <<<(NN + 255) / 256, 256>>>();

    k_sgemm1<<<dim3((NN + 127) / 128, 1), 256>>>(x, W1, b1);
    k_scatter128<<<(E * 32 + 255) / 256, 256>>>(src, dst, E);

    k_sgemm2<<<dim3((NN + 127) / 128, 1), 256>>>(W2, b2);
    k_scatter64<<<(E * 16 + 255) / 256, 256>>>(src, dst, E);

    k_score<<<(SE * 16 + 255) / 256, 256>>>(pos, neg, EPn, SE, out);

    int tail = out_size - SE;
    if (tail > 0) k_zero_tail<<<(tail + 255) / 256, 256>>>(out + SE, tail);
}

// round 3
// speedup vs baseline: 1.6318x; 1.4637x over previous
#include <cuda_runtime.h>

#define NN   100000
#define FIN  256
#define HDIM 128
#define CDIM 64
#define MAXE 1600000
#define NB   ((NN + 255) / 256)   // scan blocks = 391

// Scratch (static device globals — allocation-free per harness rules)
__device__ int   g_degi[NN];
__device__ int   g_rowptr[NN + 1];
__device__ int   g_bsum[NB];
__device__ int   g_boff[NB];
__device__ int   g_cursor[NN];
__device__ int   g_esrc[MAXE];        // edge sources grouped by dst (CSR)
__device__ float g_dis[NN];
__device__ float g_hw1[NN * HDIM];    // x @ W1
__device__ float g_agg1[NN * HDIM];   // layer-1 aggregate (self + msgs + b1)
__device__ float g_hw2[NN * CDIM];    // relu(agg1) @ W2
__device__ float g_agg2[NN * CDIM];   // final h2

__device__ __forceinline__ void cp_async16(void* smem, const void* gmem) {
    unsigned s = (unsigned)__cvta_generic_to_shared(smem);
    asm volatile("cp.async.ca.shared.global [%0], [%1], 16;\n" :: "r"(s), "l"(gmem));
}
__device__ __forceinline__ void cp_commit() { asm volatile("cp.async.commit_group;\n"); }
__device__ __forceinline__ void cp_wait0()  { asm volatile("cp.async.wait_group 0;\n" ::: "memory"); }

// ───────────────────────── CSR build ─────────────────────────
__global__ void k_zero_deg() {
    int i = blockIdx.x * blockDim.x + threadIdx.x;
    if (i < NN) g_degi[i] = 0;
}

__global__ void k_count_deg(const int* __restrict__ dst, int E) {
    int e = blockIdx.x * blockDim.x + threadIdx.x;
    if (e < E) atomicAdd(&g_degi[dst[e]], 1);
}

__global__ void k_scan1() {
    __shared__ int sm[256];
    int i = blockIdx.x * 256 + threadIdx.x;
    int v = (i < NN) ? g_degi[i] : 0;
    sm[threadIdx.x] = v;
    __syncthreads();
    #pragma unroll
    for (int o = 1; o < 256; o <<= 1) {
        int t = (threadIdx.x >= o) ? sm[threadIdx.x - o] : 0;
        __syncthreads();
        sm[threadIdx.x] += t;
        __syncthreads();
    }
    if (i < NN) g_rowptr[i] = sm[threadIdx.x] - v;    // exclusive, block-local
    if (threadIdx.x == 255) g_bsum[blockIdx.x] = sm[255];
}

__global__ void k_scan2() {
    __shared__ int sm[512];
    int v = (threadIdx.x < NB) ? g_bsum[threadIdx.x] : 0;
    sm[threadIdx.x] = v;
    __syncthreads();
    #pragma unroll
    for (int o = 1; o < 512; o <<= 1) {
        int t = (threadIdx.x >= o) ? sm[threadIdx.x - o] : 0;
        __syncthreads();
        sm[threadIdx.x] += t;
        __syncthreads();
    }
    if (threadIdx.x < NB) g_boff[threadIdx.x] = sm[threadIdx.x] - v;  // exclusive
}

__global__ void k_scan3(int E) {
    int i = blockIdx.x * blockDim.x + threadIdx.x;
    if (i < NN) {
        int r = g_rowptr[i] + g_boff[i >> 8];
        g_rowptr[i] = r;
        g_cursor[i] = r;
        g_dis[i]    = rsqrtf((float)g_degi[i] + 1.0f);
    }
    if (i == 0) g_rowptr[NN] = E;
}

__global__ void k_bin(const int* __restrict__ src, const int* __restrict__ dst, int E) {
    int e = blockIdx.x * blockDim.x + threadIdx.x;
    if (e >= E) return;
    int d = dst[e];
    int p = atomicAdd(&g_cursor[d], 1);
    g_esrc[p] = src[e];
}

// ───────────────────────── GEMMs ─────────────────────────
// Double-buffered tiled SGEMM; writes C = A@B (optionally relu on A load).
template<int BM, int BN, int BK, int TM, int TN, bool RELU_A>
__device__ __forceinline__ void sgemm_db(
    int M, int Nn, int K,
    const float* __restrict__ A, const float* __restrict__ B,
    float* __restrict__ Cm)
{
    constexpr int NT  = (BM / TM) * (BN / TN);
    constexpr int AIT = (BM * BK / 4) / NT;
    constexpr int BIT = (BK * BN / 4) / NT;

    __shared__ float As[2][BK][BM];
    __shared__ float Bs[2][BK][BN];

    const int tid  = threadIdx.x;
    const int brow = blockIdx.x * BM;
    const int bcol = blockIdx.y * BN;
    const int tcol = tid % (BN / TN);
    const int trow = tid / (BN / TN);

    float acc[TM][TN];
    #pragma unroll
    for (int i = 0; i < TM; i++)
        #pragma unroll
        for (int j = 0; j < TN; j++) acc[i][j] = 0.0f;

    float4 areg[AIT];
    int arow[AIT], akk[AIT];
    #pragma unroll
    for (int it = 0; it < AIT; it++) {
        int idx = tid + it * NT;
        arow[it] = idx / (BK / 4);
        akk[it]  = (idx % (BK / 4)) * 4;
    }

    auto ldgA = [&](int k0) {
        #pragma unroll
        for (int it = 0; it < AIT; it++) {
            int grow = brow + arow[it];
            float4 v = make_float4(0.f, 0.f, 0.f, 0.f);
            if (grow < M) v = *(const float4*)(A + (long long)grow * K + k0 + akk[it]);
            if (RELU_A) {
                v.x = fmaxf(v.x, 0.f); v.y = fmaxf(v.y, 0.f);
                v.z = fmaxf(v.z, 0.f); v.w = fmaxf(v.w, 0.f);
            }
            areg[it] = v;
        }
    };
    auto stsA = [&](int buf) {
        #pragma unroll
        for (int it = 0; it < AIT; it++) {
            As[buf][akk[it] + 0][arow[it]] = areg[it].x;
            As[buf][akk[it] + 1][arow[it]] = areg[it].y;
            As[buf][akk[it] + 2][arow[it]] = areg[it].z;
            As[buf][akk[it] + 3][arow[it]] = areg[it].w;
        }
    };
    auto cpB = [&](int buf, int k0) {
        #pragma unroll
        for (int it = 0; it < BIT; it++) {
            int idx = (tid + it * NT) * 4;
            int kk  = idx / BN;
            int col = idx % BN;
            cp_async16(&Bs[buf][kk][col],
                       B + (long long)(k0 + kk) * Nn + bcol + col);
        }
        cp_commit();
    };
    auto compute = [&](int buf) {
        #pragma unroll
        for (int kk = 0; kk < BK; kk++) {
            float ra[TM], rb[TN];
            #pragma unroll
            for (int i = 0; i < TM; i++) ra[i] = As[buf][kk][trow * TM + i];
            #pragma unroll
            for (int j = 0; j < TN; j++) rb[j] = Bs[buf][kk][tcol * TN + j];
            #pragma unroll
            for (int i = 0; i < TM; i++)
                #pragma unroll
                for (int j = 0; j < TN; j++)
                    acc[i][j] += ra[i] * rb[j];
        }
    };

    ldgA(0);
    cpB(0, 0);
    stsA(0);
    cp_wait0();
    __syncthreads();

    const int NIT = K / BK;
    for (int it = 1; it < NIT; it++) {
        int cur = (it - 1) & 1, nxt = it & 1;
        ldgA(it * BK);
        cpB(nxt, it * BK);
        compute(cur);
        stsA(nxt);
        cp_wait0();
        __syncthreads();
    }
    compute((NIT - 1) & 1);

    #pragma unroll
    for (int i = 0; i < TM; i++) {
        int grow = brow + trow * TM + i;
        if (grow >= M) break;
        #pragma unroll
        for (int j = 0; j < TN; j += 4) {
            int gcol = bcol + tcol * TN + j;
            float4 v = make_float4(acc[i][j], acc[i][j+1], acc[i][j+2], acc[i][j+3]);
            *(float4*)(Cm + (long long)grow * Nn + gcol) = v;
        }
    }
}

__global__ void __launch_bounds__(256, 2)
k_sgemm1(const float* __restrict__ x, const float* __restrict__ W1)
{
    sgemm_db<128, 128, 16, 8, 8, false>(NN, HDIM, FIN, x, W1, g_hw1);
}

__global__ void __launch_bounds__(256, 2)
k_sgemm2(const float* __restrict__ W2)
{
    sgemm_db<128, 64, 16, 8, 4, true>(NN, CDIM, HDIM, g_agg1, W2, g_hw2);
}

// ───────────────────────── gather aggregation (no float atomics) ─────────────────────────
// Layer 1: one warp per node, 128 floats = float4/lane. acc = hw1[v]*dis²
// + Σ_e dis[s]dis[v]*hw1[s] + b1.
__global__ void k_gather1(const float* __restrict__ b1) {
    int t = blockIdx.x * blockDim.x + threadIdx.x;
    int v = t >> 5, lane = t & 31;
    if (v >= NN) return;
    int beg = g_rowptr[v], end = g_rowptr[v + 1];
    float dv = g_dis[v];
    const float4* hw = (const float4*)g_hw1;
    float4 a = hw[(long long)v * 32 + lane];
    float d2 = dv * dv;
    float4 acc = make_float4(a.x * d2, a.y * d2, a.z * d2, a.w * d2);

    int p = beg;
    int s0 = (p < end) ? __ldg(&g_esrc[p]) : 0;
    for (; p < end; p++) {
        int s1 = (p + 1 < end) ? __ldg(&g_esrc[p + 1]) : 0;
        float c = dv * g_dis[s0];
        float4 m = hw[(long long)s0 * 32 + lane];
        acc.x += c * m.x; acc.y += c * m.y;
        acc.z += c * m.z; acc.w += c * m.w;
        s0 = s1;
    }
    float4 bb = ((const float4*)b1)[lane];
    acc.x += bb.x; acc.y += bb.y; acc.z += bb.z; acc.w += bb.w;
    ((float4*)g_agg1)[(long long)v * 32 + lane] = acc;
}

// Layer 2: 16 lanes per node (64 floats = float4/sublane), 2 nodes per warp.
__global__ void k_gather2(const float* __restrict__ b2) {
    int t = blockIdx.x * blockDim.x + threadIdx.x;
    int v = t >> 4, lane = t & 15;
    if (v >= NN) return;
    int beg = g_rowptr[v], end = g_rowptr[v + 1];
    float dv = g_dis[v];
    const float4* hw = (const float4*)g_hw2;
    float4 a = hw[(long long)v * 16 + lane];
    float d2 = dv * dv;
    float4 acc = make_float4(a.x * d2, a.y * d2, a.z * d2, a.w * d2);

    int p = beg;
    int s0 = (p < end) ? __ldg(&g_esrc[p]) : 0;
    for (; p < end; p++) {
        int s1 = (p + 1 < end) ? __ldg(&g_esrc[p + 1]) : 0;
        float c = dv * g_dis[s0];
        float4 m = hw[(long long)s0 * 16 + lane];
        acc.x += c * m.x; acc.y += c * m.y;
        acc.z += c * m.z; acc.w += c * m.w;
        s0 = s1;
    }
    float4 bb = ((const float4*)b2)[lane];
    acc.x += bb.x; acc.y += bb.y; acc.z += bb.z; acc.w += bb.w;
    ((float4*)g_agg2)[(long long)v * 16 + lane] = acc;
}

// ───────────────────────── scoring ─────────────────────────
__global__ void k_score(const int* __restrict__ pos, const int* __restrict__ neg,
                        int EPn, int SE, float* __restrict__ out)
{
    int t = blockIdx.x * blockDim.x + threadIdx.x;
    int e = t >> 4, lane = t & 15;
    if (e >= SE) return;
    int i, j;
    if (e < EPn) { j = pos[e];       i = pos[e + EPn]; }
    else         { j = neg[e - EPn]; i = neg[e];       }
    float4 a = ((const float4*)(g_agg2 + (long long)i * CDIM))[lane];
    float4 b = ((const float4*)(g_agg2 + (long long)j * CDIM))[lane];
    float s = a.x * b.x + a.y * b.y + a.z * b.z + a.w * b.w;
    #pragma unroll
    for (int o = 8; o; o >>= 1) s += __shfl_xor_sync(0xffffffffu, s, o);
    if (lane == 0) out[e] = s;
}

__global__ void k_zero_tail(float* __restrict__ out, int n) {
    int i = blockIdx.x * blockDim.x + threadIdx.x;
    if (i < n) out[i] = 0.0f;
}

extern "C" void kernel_launch(void* const* d_in, const int* in_sizes, int n_in,
                              void* d_out, int out_size)
{
    const float* x   = (const float*)d_in[0];
    // d_in[1] = masked_nodes (unused by the reference output)
    const int*   pos = (const int*)d_in[2];
    const int*   neg = (const int*)d_in[3];
    const int*   ei  = (const int*)d_in[4];
    const float* W1  = (const float*)d_in[5];
    const float* b1  = (const float*)d_in[6];
    const float* W2  = (const float*)d_in[7];
    const float* b2  = (const float*)d_in[8];
    float* out = (float*)d_out;

    const int E   = in_sizes[4] / 2;
    const int EPn = in_sizes[2] / 2;
    const int SE  = 2 * EPn;
    const int* src = ei;
    const int* dst = ei + E;

    // CSR build
    k_zero_deg <<<(NN + 255) / 256, 256>>>();
    k_count_deg<<<(E + 255) / 256, 256>>>(dst, E);
    k_scan1<<<NB, 256>>>();
    k_scan2<<<1, 512>>>();
    k_scan3<<<(NN + 255) / 256, 256>>>(E);
    k_bin  <<<(E + 255) / 256, 256>>>(src, dst, E);

    // Layer 1
    k_sgemm1 <<<dim3((NN + 127) / 128, 1), 256>>>(x, W1);
    k_gather1<<<(NN * 32 + 255) / 256, 256>>>(b1);

    // Layer 2
    k_sgemm2 <<<dim3((NN + 127) / 128, 1), 256>>>(W2);
    k_gather2<<<(NN * 16 + 255) / 256, 256>>>(b2);

    // Scoring
    k_score<<<(SE * 16 + 255) / 256, 256>>>(pos, neg, EPn, SE, out);

    int tail = out_size - SE;
    if (tail > 0) k_zero_tail<<<(tail + 255) / 256, 256>>>(out + SE, tail);
}

// round 6
// speedup vs baseline: 2.4232x; 1.4850x over previous
#include <cuda_runtime.h>

#define NN   100000
#define FIN  256
#define HDIM 128
#define CDIM 64
#define MAXE 1600000
#define NB   ((NN + 255) / 256)   // scan blocks = 391

// Scratch (static device globals — allocation-free per harness rules)
__device__ int   g_degi[NN];
__device__ int   g_rowptr[NN + 1];
__device__ int   g_bsum[NB];
__device__ int   g_boff[NB];
__device__ int   g_cursor[NN];
__device__ int   g_esrc[MAXE];        // edge sources grouped by dst (CSR)
__device__ float g_dis[NN];
__device__ float g_hw1[NN * HDIM];    // dis[v] * (x @ W1)[v]     (pre-scaled)
__device__ float g_agg1[NN * HDIM];   // relu(layer-1 aggregate)
__device__ float g_hw2[NN * CDIM];    // dis[v] * (agg1 @ W2)[v]  (pre-scaled)
__device__ float g_agg2[NN * CDIM];   // final h2

__device__ __forceinline__ void cp_async16(void* smem, const void* gmem) {
    unsigned s = (unsigned)__cvta_generic_to_shared(smem);
    asm volatile("cp.async.ca.shared.global [%0], [%1], 16;\n" :: "r"(s), "l"(gmem));
}
__device__ __forceinline__ void cp_commit() { asm volatile("cp.async.commit_group;\n"); }
__device__ __forceinline__ void cp_wait0()  { asm volatile("cp.async.wait_group 0;\n" ::: "memory"); }

__device__ __forceinline__ unsigned f2tf32(float f) {
    unsigned u;
    asm("cvt.rna.tf32.f32 %0, %1;\n" : "=r"(u) : "f"(f));
    return u;
}

__device__ __forceinline__ void mma_tf32(float* d, const unsigned* a, const unsigned* b) {
    asm volatile(
        "mma.sync.aligned.m16n8k8.row.col.f32.tf32.tf32.f32 "
        "{%0,%1,%2,%3}, {%4,%5,%6,%7}, {%8,%9}, {%0,%1,%2,%3};\n"
        : "+f"(d[0]), "+f"(d[1]), "+f"(d[2]), "+f"(d[3])
        : "r"(a[0]), "r"(a[1]), "r"(a[2]), "r"(a[3]), "r"(b[0]), "r"(b[1]));
}

// ───────────────────────── CSR build ─────────────────────────
__global__ void k_zero_deg() {
    int i = blockIdx.x * blockDim.x + threadIdx.x;
    if (i < NN) g_degi[i] = 0;
}

__global__ void k_count_deg(const int* __restrict__ dst, int E) {
    int e = blockIdx.x * blockDim.x + threadIdx.x;
    if (e < E) atomicAdd(&g_degi[dst[e]], 1);
}

__global__ void k_scan1() {
    __shared__ int sm[256];
    int i = blockIdx.x * 256 + threadIdx.x;
    int v = (i < NN) ? g_degi[i] : 0;
    sm[threadIdx.x] = v;
    __syncthreads();
    #pragma unroll
    for (int o = 1; o < 256; o <<= 1) {
        int t = (threadIdx.x >= o) ? sm[threadIdx.x - o] : 0;
        __syncthreads();
        sm[threadIdx.x] += t;
        __syncthreads();
    }
    if (i < NN) g_rowptr[i] = sm[threadIdx.x] - v;
    if (threadIdx.x == 255) g_bsum[blockIdx.x] = sm[255];
}

__global__ void k_scan2() {
    __shared__ int sm[512];
    int v = (threadIdx.x < NB) ? g_bsum[threadIdx.x] : 0;
    sm[threadIdx.x] = v;
    __syncthreads();
    #pragma unroll
    for (int o = 1; o < 512; o <<= 1) {
        int t = (threadIdx.x >= o) ? sm[threadIdx.x - o] : 0;
        __syncthreads();
        sm[threadIdx.x] += t;
        __syncthreads();
    }
    if (threadIdx.x < NB) g_boff[threadIdx.x] = sm[threadIdx.x] - v;
}

__global__ void k_scan3(int E) {
    int i = blockIdx.x * blockDim.x + threadIdx.x;
    if (i < NN) {
        int r = g_rowptr[i] + g_boff[i >> 8];
        g_rowptr[i] = r;
        g_cursor[i] = r;
        g_dis[i]    = rsqrtf((float)g_degi[i] + 1.0f);
    }
    if (i == 0) g_rowptr[NN] = E;
}

__global__ void k_bin(const int* __restrict__ src, const int* __restrict__ dst, int E) {
    int e = blockIdx.x * blockDim.x + threadIdx.x;
    if (e >= E) return;
    int d = dst[e];
    int p = atomicAdd(&g_cursor[d], 1);
    g_esrc[p] = src[e];
}

// ───────────────────────── TF32 tensor-core GEMM ─────────────────────────
// C[row] = g_dis[row] * (A @ B)[row].  A: [M,K] row-major, B: [K,N] row-major.
// NOTE: device function — all g_* pointers must be resolved in DEVICE code
// (host-side decay of __device__ globals passes the host shadow address).
template<int BM, int BN, int BK, int WM, int WN, int NT>
__device__ __forceinline__ void mma_body(
    const float* __restrict__ A, const float* __restrict__ Bg,
    float* __restrict__ C, int M, int N, int K)
{
    constexpr int BKp = BK + 4;        // A row pad (16B-aligned, spreads banks)
    constexpr int BNp = BN + 8;        // B row pad (stride%32 = 8 -> conflict-free)
    __shared__ float As[2][BM][BKp];
    __shared__ float Bs[2][BK][BNp];

    const int tid  = threadIdx.x;
    const int wid  = tid >> 5;
    const int lane = tid & 31;
    const int grp  = lane >> 2;        // 0..7
    const int qi   = lane & 3;         // 0..3
    constexpr int NWN = BN / WN;
    const int warp_m = wid / NWN;
    const int warp_n = wid % NWN;
    constexpr int MF = WM / 16;
    constexpr int NF = WN / 8;

    const int brow = blockIdx.x * BM;

    float acc[MF][NF][4];
    #pragma unroll
    for (int i = 0; i < MF; i++)
        #pragma unroll
        for (int j = 0; j < NF; j++)
            #pragma unroll
            for (int q = 0; q < 4; q++) acc[i][j][q] = 0.0f;

    constexpr int AIT = (BM * BK / 4) / NT;
    constexpr int BIT = (BK * BN / 4) / NT;

    auto cpA = [&](int buf, int k0) {
        #pragma unroll
        for (int it = 0; it < AIT; it++) {
            int idx  = tid + it * NT;
            int row  = idx / (BK / 4);
            int kc   = (idx % (BK / 4)) * 4;
            int grow = brow + row;
            if (grow > M - 1) grow = M - 1;   // clamp: rows >= M never stored
            cp_async16(&As[buf][row][kc], A + (long long)grow * K + k0 + kc);
        }
    };
    auto cpB = [&](int buf, int k0) {
        #pragma unroll
        for (int it = 0; it < BIT; it++) {
            int idx = tid + it * NT;
            int kk  = idx / (BN / 4);
            int nc  = (idx % (BN / 4)) * 4;
            cp_async16(&Bs[buf][kk][nc], Bg + (long long)(k0 + kk) * N + nc);
        }
    };
    auto compute = [&](int buf) {
        #pragma unroll
        for (int ks = 0; ks < BK / 8; ks++) {
            int kk = ks * 8;
            unsigned a[MF][4], b[NF][2];
            #pragma unroll
            for (int fm = 0; fm < MF; fm++) {
                const float* ap = &As[buf][warp_m * WM + fm * 16 + grp][kk + qi];
                a[fm][0] = f2tf32(ap[0]);
                a[fm][1] = f2tf32(ap[8 * BKp]);
                a[fm][2] = f2tf32(ap[4]);
                a[fm][3] = f2tf32(ap[8 * BKp + 4]);
            }
            #pragma unroll
            for (int fn = 0; fn < NF; fn++) {
                const float* bp = &Bs[buf][kk + qi][warp_n * WN + fn * 8 + grp];
                b[fn][0] = f2tf32(bp[0]);
                b[fn][1] = f2tf32(bp[4 * BNp]);
            }
            #pragma unroll
            for (int fm = 0; fm < MF; fm++)
                #pragma unroll
                for (int fn = 0; fn < NF; fn++)
                    mma_tf32(acc[fm][fn], a[fm], b[fn]);
        }
    };

    cpA(0, 0); cpB(0, 0); cp_commit();
    cp_wait0(); __syncthreads();

    const int KT = K / BK;
    for (int t = 1; t < KT; t++) {
        cpA(t & 1, t * BK); cpB(t & 1, t * BK); cp_commit();
        compute((t - 1) & 1);
        cp_wait0(); __syncthreads();
    }
    compute((KT - 1) & 1);

    // Epilogue: scale row by g_dis[row], store float2 pairs.
    #pragma unroll
    for (int fm = 0; fm < MF; fm++) {
        int r0 = brow + warp_m * WM + fm * 16 + grp;
        int r1 = r0 + 8;
        float d0 = (r0 < M) ? g_dis[r0] : 0.0f;
        float d1 = (r1 < M) ? g_dis[r1] : 0.0f;
        #pragma unroll
        for (int fn = 0; fn < NF; fn++) {
            int col = warp_n * WN + fn * 8 + 2 * qi;
            if (r0 < M) {
                float2 v = make_float2(acc[fm][fn][0] * d0, acc[fm][fn][1] * d0);
                *(float2*)(C + (long long)r0 * N + col) = v;
            }
            if (r1 < M) {
                float2 v = make_float2(acc[fm][fn][2] * d1, acc[fm][fn][3] * d1);
                *(float2*)(C + (long long)r1 * N + col) = v;
            }
        }
    }
}

// Wrappers: resolve __device__ globals inside device code.
__global__ void __launch_bounds__(256)
k_gemm1(const float* __restrict__ x, const float* __restrict__ W1)
{
    mma_body<128, 128, 16, 64, 32, 256>(x, W1, g_hw1, NN, HDIM, FIN);
}

__global__ void __launch_bounds__(256)
k_gemm2(const float* __restrict__ W2)
{
    mma_body<128, 64, 16, 32, 32, 256>(g_agg1, W2, g_hw2, NN, CDIM, HDIM);
}

// ───────────────────────── gather aggregation ─────────────────────────
// hw is pre-scaled by dis[src].  out = dv * (hw[v] + Σ_e hw[src]) + bias.
// Layer 1 additionally applies relu (agg1 is only ever consumed as relu(agg1)).
__global__ void k_gather1(const float* __restrict__ b1) {
    int t = blockIdx.x * blockDim.x + threadIdx.x;
    int v = t >> 5, lane = t & 31;
    if (v >= NN) return;
    int beg = g_rowptr[v], end = g_rowptr[v + 1];
    float dv = g_dis[v];
    const float4* hw = (const float4*)g_hw1;
    float4 acc  = hw[(long long)v * 32 + lane];
    float4 acc2 = make_float4(0.f, 0.f, 0.f, 0.f);

    int p = beg;
    for (; p + 1 < end; p += 2) {
        int sa = __ldg(&g_esrc[p]);
        int sb = __ldg(&g_esrc[p + 1]);
        float4 ma = hw[(long long)sa * 32 + lane];
        float4 mb = hw[(long long)sb * 32 + lane];
        acc.x  += ma.x; acc.y  += ma.y; acc.z  += ma.z; acc.w  += ma.w;
        acc2.x += mb.x; acc2.y += mb.y; acc2.z += mb.z; acc2.w += mb.w;
    }
    if (p < end) {
        int sa = __ldg(&g_esrc[p]);
        float4 ma = hw[(long long)sa * 32 + lane];
        acc.x += ma.x; acc.y += ma.y; acc.z += ma.z; acc.w += ma.w;
    }
    acc.x += acc2.x; acc.y += acc2.y; acc.z += acc2.z; acc.w += acc2.w;

    float4 bb = ((const float4*)b1)[lane];
    acc.x = fmaxf(acc.x * dv + bb.x, 0.f);
    acc.y = fmaxf(acc.y * dv + bb.y, 0.f);
    acc.z = fmaxf(acc.z * dv + bb.z, 0.f);
    acc.w = fmaxf(acc.w * dv + bb.w, 0.f);
    ((float4*)g_agg1)[(long long)v * 32 + lane] = acc;
}

__global__ void k_gather2(const float* __restrict__ b2) {
    int t = blockIdx.x * blockDim.x + threadIdx.x;
    int v = t >> 4, lane = t & 15;
    if (v >= NN) return;
    int beg = g_rowptr[v], end = g_rowptr[v + 1];
    float dv = g_dis[v];
    const float4* hw = (const float4*)g_hw2;
    float4 acc  = hw[(long long)v * 16 + lane];
    float4 acc2 = make_float4(0.f, 0.f, 0.f, 0.f);

    int p = beg;
    for (; p + 1 < end; p += 2) {
        int sa = __ldg(&g_esrc[p]);
        int sb = __ldg(&g_esrc[p + 1]);
        float4 ma = hw[(long long)sa * 16 + lane];
        float4 mb = hw[(long long)sb * 16 + lane];
        acc.x  += ma.x; acc.y  += ma.y; acc.z  += ma.z; acc.w  += ma.w;
        acc2.x += mb.x; acc2.y += mb.y; acc2.z += mb.z; acc2.w += mb.w;
    }
    if (p < end) {
        int sa = __ldg(&g_esrc[p]);
        float4 ma = hw[(long long)sa * 16 + lane];
        acc.x += ma.x; acc.y += ma.y; acc.z += ma.z; acc.w += ma.w;
    }
    acc.x += acc2.x; acc.y += acc2.y; acc.z += acc2.z; acc.w += acc2.w;

    float4 bb = ((const float4*)b2)[lane];
    acc.x = acc.x * dv + bb.x;
    acc.y = acc.y * dv + bb.y;
    acc.z = acc.z * dv + bb.z;
    acc.w = acc.w * dv + bb.w;
    ((float4*)g_agg2)[(long long)v * 16 + lane] = acc;
}

// ───────────────────────── scoring ─────────────────────────
__global__ void k_score(const int* __restrict__ pos, const int* __restrict__ neg,
                        int EPn, int SE, float* __restrict__ out)
{
    int t = blockIdx.x * blockDim.x + threadIdx.x;
    int e = t >> 4, lane = t & 15;
    if (e >= SE) return;
    int i, j;
    if (e < EPn) { j = pos[e];       i = pos[e + EPn]; }
    else         { j = neg[e - EPn]; i = neg[e];       }
    float4 a = ((const float4*)(g_agg2 + (long long)i * CDIM))[lane];
    float4 b = ((const float4*)(g_agg2 + (long long)j * CDIM))[lane];
    float s = a.x * b.x + a.y * b.y + a.z * b.z + a.w * b.w;
    #pragma unroll
    for (int o = 8; o; o >>= 1) s += __shfl_xor_sync(0xffffffffu, s, o);
    if (lane == 0) out[e] = s;
}

__global__ void k_zero_tail(float* __restrict__ out, int n) {
    int i = blockIdx.x * blockDim.x + threadIdx.x;
    if (i < n) out[i] = 0.0f;
}

extern "C" void kernel_launch(void* const* d_in, const int* in_sizes, int n_in,
                              void* d_out, int out_size)
{
    const float* x   = (const float*)d_in[0];
    // d_in[1] = masked_nodes (unused by the reference output)
    const int*   pos = (const int*)d_in[2];
    const int*   neg = (const int*)d_in[3];
    const int*   ei  = (const int*)d_in[4];
    const float* W1  = (const float*)d_in[5];
    const float* b1  = (const float*)d_in[6];
    const float* W2  = (const float*)d_in[7];
    const float* b2  = (const float*)d_in[8];
    float* out = (float*)d_out;

    const int E   = in_sizes[4] / 2;
    const int EPn = in_sizes[2] / 2;
    const int SE  = 2 * EPn;
    const int* src = ei;
    const int* dst = ei + E;

    // CSR build
    k_zero_deg <<<(NN + 255) / 256, 256>>>();
    k_count_deg<<<(E + 255) / 256, 256>>>(dst, E);
    k_scan1<<<NB, 256>>>();
    k_scan2<<<1, 512>>>();
    k_scan3<<<(NN + 255) / 256, 256>>>(E);
    k_bin  <<<(E + 255) / 256, 256>>>(src, dst, E);

    // Layer 1
    k_gemm1<<<(NN + 127) / 128, 256>>>(x, W1);
    k_gather1<<<(NN * 32 + 255) / 256, 256>>>(b1);

    // Layer 2
    k_gemm2<<<(NN + 127) / 128, 256>>>(W2);
    k_gather2<<<(NN * 16 + 255) / 256, 256>>>(b2);

    // Scoring
    k_score<<<(SE * 16 + 255) / 256, 256>>>(pos, neg, EPn, SE, out);

    int tail = out_size - SE;
    if (tail > 0) k_zero_tail<<<(tail + 255) / 256, 256>>>(out + SE, tail);
}

// round 7
// speedup vs baseline: 2.4596x; 1.0150x over previous
#include <cuda_runtime.h>
#include <cuda_fp16.h>

#define NN   100000
#define FIN  256
#define HDIM 128
#define CDIM 64
#define MAXE 1600000
#define NB   ((NN + 255) / 256)   // scan blocks = 391

// Scratch (static device globals — allocation-free per harness rules)
__device__ int     g_degi[NN];
__device__ int     g_rowptr[NN + 1];
__device__ int     g_bsum[NB];
__device__ int     g_boff[NB];
__device__ int     g_cursor[NN];
__device__ int     g_esrc[MAXE];            // edge sources grouped by dst (CSR)
__device__ float   g_dis[NN];
__device__ __half2 g_hw1h[NN * HDIM / 2];   // fp16: dis[v]*(x@W1)[v]
__device__ float   g_agg1[NN * HDIM];       // fp32: relu(layer-1 aggregate)
__device__ __half2 g_hw2h[NN * CDIM / 2];   // fp16: dis[v]*(agg1@W2)[v]
__device__ __half2 g_agg2h[NN * CDIM / 2];  // fp16: final h2

__device__ __forceinline__ void cp_async16(void* smem, const void* gmem) {
    unsigned s = (unsigned)__cvta_generic_to_shared(smem);
    asm volatile("cp.async.ca.shared.global [%0], [%1], 16;\n" :: "r"(s), "l"(gmem));
}
__device__ __forceinline__ void cp_commit() { asm volatile("cp.async.commit_group;\n"); }
__device__ __forceinline__ void cp_wait0()  { asm volatile("cp.async.wait_group 0;\n" ::: "memory"); }

__device__ __forceinline__ unsigned f2tf32(float f) {
    unsigned u;
    asm("cvt.rna.tf32.f32 %0, %1;\n" : "=r"(u) : "f"(f));
    return u;
}

__device__ __forceinline__ void mma_tf32(float* d, const unsigned* a, const unsigned* b) {
    asm volatile(
        "mma.sync.aligned.m16n8k8.row.col.f32.tf32.tf32.f32 "
        "{%0,%1,%2,%3}, {%4,%5,%6,%7}, {%8,%9}, {%0,%1,%2,%3};\n"
        : "+f"(d[0]), "+f"(d[1]), "+f"(d[2]), "+f"(d[3])
        : "r"(a[0]), "r"(a[1]), "r"(a[2]), "r"(a[3]), "r"(b[0]), "r"(b[1]));
}

// ───────────────────────── CSR build ─────────────────────────
__global__ void k_zero_deg() {
    int i = blockIdx.x * blockDim.x + threadIdx.x;
    if (i < NN) g_degi[i] = 0;
}

__global__ void k_count_deg(const int* __restrict__ dst, int E) {
    int e = blockIdx.x * blockDim.x + threadIdx.x;
    if (e < E) atomicAdd(&g_degi[dst[e]], 1);
}

__global__ void k_scan1() {
    __shared__ int sm[256];
    int i = blockIdx.x * 256 + threadIdx.x;
    int v = (i < NN) ? g_degi[i] : 0;
    sm[threadIdx.x] = v;
    __syncthreads();
    #pragma unroll
    for (int o = 1; o < 256; o <<= 1) {
        int t = (threadIdx.x >= o) ? sm[threadIdx.x - o] : 0;
        __syncthreads();
        sm[threadIdx.x] += t;
        __syncthreads();
    }
    if (i < NN) g_rowptr[i] = sm[threadIdx.x] - v;
    if (threadIdx.x == 255) g_bsum[blockIdx.x] = sm[255];
}

__global__ void k_scan2() {
    __shared__ int sm[512];
    int v = (threadIdx.x < NB) ? g_bsum[threadIdx.x] : 0;
    sm[threadIdx.x] = v;
    __syncthreads();
    #pragma unroll
    for (int o = 1; o < 512; o <<= 1) {
        int t = (threadIdx.x >= o) ? sm[threadIdx.x - o] : 0;
        __syncthreads();
        sm[threadIdx.x] += t;
        __syncthreads();
    }
    if (threadIdx.x < NB) g_boff[threadIdx.x] = sm[threadIdx.x] - v;
}

__global__ void k_scan3(int E) {
    int i = blockIdx.x * blockDim.x + threadIdx.x;
    if (i < NN) {
        int r = g_rowptr[i] + g_boff[i >> 8];
        g_rowptr[i] = r;
        g_cursor[i] = r;
        g_dis[i]    = rsqrtf((float)g_degi[i] + 1.0f);
    }
    if (i == 0) g_rowptr[NN] = E;
}

__global__ void k_bin(const int* __restrict__ src, const int* __restrict__ dst, int E) {
    int e = blockIdx.x * blockDim.x + threadIdx.x;
    if (e >= E) return;
    int d = dst[e];
    int p = atomicAdd(&g_cursor[d], 1);
    g_esrc[p] = src[e];
}

// ───────────────────────── TF32 tensor-core GEMM ─────────────────────────
// C[row] = fp16( g_dis[row] * (A @ B)[row] ).  A: [M,K] fp32 row-major,
// B: [K,N] fp32 row-major, C: fp16 (half2) row-major.
// NOTE: device function — g_* pointers must be resolved in DEVICE code.
template<int BM, int BN, int BK, int WM, int WN, int NT>
__device__ __forceinline__ void mma_body(
    const float* __restrict__ A, const float* __restrict__ Bg,
    __half2* __restrict__ C, int M, int N, int K)
{
    constexpr int BKp = BK + 4;        // A row pad (16B-aligned, spreads banks)
    constexpr int BNp = BN + 8;        // B row pad (stride%32 = 8 -> conflict-free)
    __shared__ float As[2][BM][BKp];
    __shared__ float Bs[2][BK][BNp];

    const int tid  = threadIdx.x;
    const int wid  = tid >> 5;
    const int lane = tid & 31;
    const int grp  = lane >> 2;        // 0..7
    const int qi   = lane & 3;         // 0..3
    constexpr int NWN = BN / WN;
    const int warp_m = wid / NWN;
    const int warp_n = wid % NWN;
    constexpr int MF = WM / 16;
    constexpr int NF = WN / 8;

    const int brow = blockIdx.x * BM;

    float acc[MF][NF][4];
    #pragma unroll
    for (int i = 0; i < MF; i++)
        #pragma unroll
        for (int j = 0; j < NF; j++)
            #pragma unroll
            for (int q = 0; q < 4; q++) acc[i][j][q] = 0.0f;

    constexpr int AIT = (BM * BK / 4) / NT;
    constexpr int BIT = (BK * BN / 4) / NT;

    auto cpA = [&](int buf, int k0) {
        #pragma unroll
        for (int it = 0; it < AIT; it++) {
            int idx  = tid + it * NT;
            int row  = idx / (BK / 4);
            int kc   = (idx % (BK / 4)) * 4;
            int grow = brow + row;
            if (grow > M - 1) grow = M - 1;   // clamp: rows >= M never stored
            cp_async16(&As[buf][row][kc], A + (long long)grow * K + k0 + kc);
        }
    };
    auto cpB = [&](int buf, int k0) {
        #pragma unroll
        for (int it = 0; it < BIT; it++) {
            int idx = tid + it * NT;
            int kk  = idx / (BN / 4);
            int nc  = (idx % (BN / 4)) * 4;
            cp_async16(&Bs[buf][kk][nc], Bg + (long long)(k0 + kk) * N + nc);
        }
    };
    auto compute = [&](int buf) {
        #pragma unroll
        for (int ks = 0; ks < BK / 8; ks++) {
            int kk = ks * 8;
            unsigned a[MF][4], b[NF][2];
            #pragma unroll
            for (int fm = 0; fm < MF; fm++) {
                const float* ap = &As[buf][warp_m * WM + fm * 16 + grp][kk + qi];
                a[fm][0] = f2tf32(ap[0]);
                a[fm][1] = f2tf32(ap[8 * BKp]);
                a[fm][2] = f2tf32(ap[4]);
                a[fm][3] = f2tf32(ap[8 * BKp + 4]);
            }
            #pragma unroll
            for (int fn = 0; fn < NF; fn++) {
                const float* bp = &Bs[buf][kk + qi][warp_n * WN + fn * 8 + grp];
                b[fn][0] = f2tf32(bp[0]);
                b[fn][1] = f2tf32(bp[4 * BNp]);
            }
            #pragma unroll
            for (int fm = 0; fm < MF; fm++)
                #pragma unroll
                for (int fn = 0; fn < NF; fn++)
                    mma_tf32(acc[fm][fn], a[fm], b[fn]);
        }
    };

    cpA(0, 0); cpB(0, 0); cp_commit();
    cp_wait0(); __syncthreads();

    const int KT = K / BK;
    for (int t = 1; t < KT; t++) {
        cpA(t & 1, t * BK); cpB(t & 1, t * BK); cp_commit();
        compute((t - 1) & 1);
        cp_wait0(); __syncthreads();
    }
    compute((KT - 1) & 1);

    // Epilogue: scale row by g_dis[row], convert to fp16, store half2.
    #pragma unroll
    for (int fm = 0; fm < MF; fm++) {
        int r0 = brow + warp_m * WM + fm * 16 + grp;
        int r1 = r0 + 8;
        float d0 = (r0 < M) ? g_dis[r0] : 0.0f;
        float d1 = (r1 < M) ? g_dis[r1] : 0.0f;
        #pragma unroll
        for (int fn = 0; fn < NF; fn++) {
            int col = warp_n * WN + fn * 8 + 2 * qi;   // even
            if (r0 < M)
                C[((long long)r0 * N + col) >> 1] =
                    __floats2half2_rn(acc[fm][fn][0] * d0, acc[fm][fn][1] * d0);
            if (r1 < M)
                C[((long long)r1 * N + col) >> 1] =
                    __floats2half2_rn(acc[fm][fn][2] * d1, acc[fm][fn][3] * d1);
        }
    }
}

// Wrappers: resolve __device__ globals inside device code.
__global__ void __launch_bounds__(256)
k_gemm1(const float* __restrict__ x, const float* __restrict__ W1)
{
    mma_body<128, 128, 16, 64, 32, 256>(x, W1, g_hw1h, NN, HDIM, FIN);
}

__global__ void __launch_bounds__(256)
k_gemm2(const float* __restrict__ W2)
{
    mma_body<128, 64, 16, 32, 32, 256>(g_agg1, W2, g_hw2h, NN, CDIM, HDIM);
}

// ───────────────────────── gather aggregation ─────────────────────────
// hw is fp16, pre-scaled by dis[src].  out = dv*(hw[v] + Σ_e hw[src]) + bias,
// accumulated in fp32.  Layer 1 applies relu and stores fp32 (gemm2 input).
__device__ __forceinline__ void acc_u2(float4& acc, uint2 u) {
    float2 f0 = __half22float2(*(__half2*)&u.x);
    float2 f1 = __half22float2(*(__half2*)&u.y);
    acc.x += f0.x; acc.y += f0.y; acc.z += f1.x; acc.w += f1.y;
}

__global__ void k_gather1(const float* __restrict__ b1) {
    int t = blockIdx.x * blockDim.x + threadIdx.x;
    int v = t >> 5, lane = t & 31;
    if (v >= NN) return;
    int beg = g_rowptr[v], end = g_rowptr[v + 1];
    float dv = g_dis[v];
    const uint2* hw = (const uint2*)g_hw1h;   // 32 uint2 per row (128 fp16)
    float4 acc  = make_float4(0.f, 0.f, 0.f, 0.f);
    float4 acc2 = make_float4(0.f, 0.f, 0.f, 0.f);
    acc_u2(acc, hw[(long long)v * 32 + lane]);   // self term

    int p = beg;
    for (; p + 1 < end; p += 2) {
        int sa = __ldg(&g_esrc[p]);
        int sb = __ldg(&g_esrc[p + 1]);
        acc_u2(acc,  hw[(long long)sa * 32 + lane]);
        acc_u2(acc2, hw[(long long)sb * 32 + lane]);
    }
    if (p < end) {
        int sa = __ldg(&g_esrc[p]);
        acc_u2(acc, hw[(long long)sa * 32 + lane]);
    }
    acc.x += acc2.x; acc.y += acc2.y; acc.z += acc2.z; acc.w += acc2.w;

    float4 bb = ((const float4*)b1)[lane];
    acc.x = fmaxf(acc.x * dv + bb.x, 0.f);
    acc.y = fmaxf(acc.y * dv + bb.y, 0.f);
    acc.z = fmaxf(acc.z * dv + bb.z, 0.f);
    acc.w = fmaxf(acc.w * dv + bb.w, 0.f);
    ((float4*)g_agg1)[(long long)v * 32 + lane] = acc;
}

__global__ void k_gather2(const float* __restrict__ b2) {
    int t = blockIdx.x * blockDim.x + threadIdx.x;
    int v = t >> 4, lane = t & 15;
    if (v >= NN) return;
    int beg = g_rowptr[v], end = g_rowptr[v + 1];
    float dv = g_dis[v];
    const uint2* hw = (const uint2*)g_hw2h;   // 16 uint2 per row (64 fp16)
    float4 acc  = make_float4(0.f, 0.f, 0.f, 0.f);
    float4 acc2 = make_float4(0.f, 0.f, 0.f, 0.f);
    acc_u2(acc, hw[(long long)v * 16 + lane]);   // self term

    int p = beg;
    for (; p + 1 < end; p += 2) {
        int sa = __ldg(&g_esrc[p]);
        int sb = __ldg(&g_esrc[p + 1]);
        acc_u2(acc,  hw[(long long)sa * 16 + lane]);
        acc_u2(acc2, hw[(long long)sb * 16 + lane]);
    }
    if (p < end) {
        int sa = __ldg(&g_esrc[p]);
        acc_u2(acc, hw[(long long)sa * 16 + lane]);
    }
    acc.x += acc2.x; acc.y += acc2.y; acc.z += acc2.z; acc.w += acc2.w;

    float4 bb = ((const float4*)b2)[lane];
    uint2 o;
    *(__half2*)&o.x = __floats2half2_rn(acc.x * dv + bb.x, acc.y * dv + bb.y);
    *(__half2*)&o.y = __floats2half2_rn(acc.z * dv + bb.z, acc.w * dv + bb.w);
    ((uint2*)g_agg2h)[(long long)v * 16 + lane] = o;
}

// ───────────────────────── scoring ─────────────────────────
__global__ void k_score(const int* __restrict__ pos, const int* __restrict__ neg,
                        int EPn, int SE, float* __restrict__ out)
{
    int t = blockIdx.x * blockDim.x + threadIdx.x;
    int e = t >> 4, lane = t & 15;
    if (e >= SE) return;
    int i, j;
    if (e < EPn) { j = pos[e];       i = pos[e + EPn]; }
    else         { j = neg[e - EPn]; i = neg[e];       }
    const uint2* h2 = (const uint2*)g_agg2h;
    uint2 ua = h2[(long long)i * 16 + lane];
    uint2 ub = h2[(long long)j * 16 + lane];
    float2 a0 = __half22float2(*(__half2*)&ua.x);
    float2 a1 = __half22float2(*(__half2*)&ua.y);
    float2 b0 = __half22float2(*(__half2*)&ub.x);
    float2 b1 = __half22float2(*(__half2*)&ub.y);
    float s = a0.x * b0.x + a0.y * b0.y + a1.x * b1.x + a1.y * b1.y;
    #pragma unroll
    for (int o = 8; o; o >>= 1) s += __shfl_xor_sync(0xffffffffu, s, o);
    if (lane == 0) out[e] = s;
}

__global__ void k_zero_tail(float* __restrict__ out, int n) {
    int i = blockIdx.x * blockDim.x + threadIdx.x;
    if (i < n) out[i] = 0.0f;
}

extern "C" void kernel_launch(void* const* d_in, const int* in_sizes, int n_in,
                              void* d_out, int out_size)
{
    const float* x   = (const float*)d_in[0];
    // d_in[1] = masked_nodes (unused by the reference output)
    const int*   pos = (const int*)d_in[2];
    const int*   neg = (const int*)d_in[3];
    const int*   ei  = (const int*)d_in[4];
    const float* W1  = (const float*)d_in[5];
    const float* b1  = (const float*)d_in[6];
    const float* W2  = (const float*)d_in[7];
    const float* b2  = (const float*)d_in[8];
    float* out = (float*)d_out;

    const int E   = in_sizes[4] / 2;
    const int EPn = in_sizes[2] / 2;
    const int SE  = 2 * EPn;
    const int* src = ei;
    const int* dst = ei + E;

    // CSR build
    k_zero_deg <<<(NN + 255) / 256, 256>>>();
    k_count_deg<<<(E + 255) / 256, 256>>>(dst, E);
    k_scan1<<<NB, 256>>>();
    k_scan2<<<1, 512>>>();
    k_scan3<<<(NN + 255) / 256, 256>>>(E);
    k_bin  <<<(E + 255) / 256, 256>>>(src, dst, E);

    // Layer 1
    k_gemm1<<<(NN + 127) / 128, 256>>>(x, W1);
    k_gather1<<<(NN * 32 + 255) / 256, 256>>>(b1);

    // Layer 2
    k_gemm2<<<(NN + 127) / 128, 256>>>(W2);
    k_gather2<<<(NN * 16 + 255) / 256, 256>>>(b2);

    // Scoring
    k_score<<<(SE * 16 + 255) / 256, 256>>>(pos, neg, EPn, SE, out);

    int tail = out_size - SE;
    if (tail > 0) k_zero_tail<<<(tail + 255) / 256, 256>>>(out + SE, tail);
}

// round 8
// speedup vs baseline: 3.0600x; 1.2441x over previous
#include <cuda_runtime.h>
#include <cuda_fp16.h>

#define NN   100000
#define FIN  256
#define HDIM 128
#define CDIM 64
#define MAXE 1600000
#define NB   ((NN + 255) / 256)   // scan blocks = 391
#define GB1  ((NN + 127) / 128)   // gemm1 blocks = 782
#define CB   391                  // histogram blocks in mega
#define ZB   128                  // tail-zero blocks in mega

// Scratch (static device globals — allocation-free per harness rules)
__device__ int     g_degi[NN];
__device__ int     g_rowptr[NN + 1];
__device__ int     g_bsum[NB];
__device__ int     g_boff[NB];
__device__ int     g_cursor[NN];
__device__ int     g_esrc[MAXE];            // edge sources grouped by dst (CSR)
__device__ float   g_dis[NN];
__device__ __half2 g_hw1h[NN * HDIM / 2];   // fp16: (x@W1)[v]  (UNSCALED)
__device__ float   g_agg1[NN * HDIM];       // fp32: relu(layer-1 aggregate)
__device__ __half2 g_hw2h[NN * CDIM / 2];   // fp16: dis[v]*(agg1@W2)[v] (pre-scaled)
__device__ __half2 g_agg2h[NN * CDIM / 2];  // fp16: final h2

__device__ __forceinline__ void cp_async16(void* smem, const void* gmem) {
    unsigned s = (unsigned)__cvta_generic_to_shared(smem);
    asm volatile("cp.async.ca.shared.global [%0], [%1], 16;\n" :: "r"(s), "l"(gmem));
}
__device__ __forceinline__ void cp_commit() { asm volatile("cp.async.commit_group;\n"); }
__device__ __forceinline__ void cp_wait0()  { asm volatile("cp.async.wait_group 0;\n" ::: "memory"); }

__device__ __forceinline__ unsigned f2tf32(float f) {
    unsigned u;
    asm("cvt.rna.tf32.f32 %0, %1;\n" : "=r"(u) : "f"(f));
    return u;
}

__device__ __forceinline__ void mma_tf32(float* d, const unsigned* a, const unsigned* b) {
    asm volatile(
        "mma.sync.aligned.m16n8k8.row.col.f32.tf32.tf32.f32 "
        "{%0,%1,%2,%3}, {%4,%5,%6,%7}, {%8,%9}, {%0,%1,%2,%3};\n"
        : "+f"(d[0]), "+f"(d[1]), "+f"(d[2]), "+f"(d[3])
        : "r"(a[0]), "r"(a[1]), "r"(a[2]), "r"(a[3]), "r"(b[0]), "r"(b[1]));
}

// Convert 8 packed halves (uint4) to 8 floats.
__device__ __forceinline__ void u4_to_f8(uint4 u, float* f) {
    float2 t;
    t = __half22float2(*(__half2*)&u.x); f[0] = t.x; f[1] = t.y;
    t = __half22float2(*(__half2*)&u.y); f[2] = t.x; f[3] = t.y;
    t = __half22float2(*(__half2*)&u.z); f[4] = t.x; f[5] = t.y;
    t = __half22float2(*(__half2*)&u.w); f[6] = t.x; f[7] = t.y;
}

// ───────────────────────── TF32 tensor-core GEMM body ─────────────────────────
// SCALE_DIS ? C = fp16(dis[row]*(A@B)) : C = fp16(A@B).
// NOTE: g_* pointers must be resolved in DEVICE code (host shadow-symbol trap).
template<int BM, int BN, int BK, int WM, int WN, int NT, bool SCALE_DIS>
__device__ __forceinline__ void mma_body(
    int bx, const float* __restrict__ A, const float* __restrict__ Bg,
    __half2* __restrict__ C, int M, int N, int K)
{
    constexpr int BKp = BK + 4;
    constexpr int BNp = BN + 8;
    __shared__ float As[2][BM][BKp];
    __shared__ float Bs[2][BK][BNp];

    const int tid  = threadIdx.x;
    const int wid  = tid >> 5;
    const int lane = tid & 31;
    const int grp  = lane >> 2;
    const int qi   = lane & 3;
    constexpr int NWN = BN / WN;
    const int warp_m = wid / NWN;
    const int warp_n = wid % NWN;
    constexpr int MF = WM / 16;
    constexpr int NF = WN / 8;

    const int brow = bx * BM;

    float acc[MF][NF][4];
    #pragma unroll
    for (int i = 0; i < MF; i++)
        #pragma unroll
        for (int j = 0; j < NF; j++)
            #pragma unroll
            for (int q = 0; q < 4; q++) acc[i][j][q] = 0.0f;

    constexpr int AIT = (BM * BK / 4) / NT;
    constexpr int BIT = (BK * BN / 4) / NT;

    auto cpA = [&](int buf, int k0) {
        #pragma unroll
        for (int it = 0; it < AIT; it++) {
            int idx  = tid + it * NT;
            int row  = idx / (BK / 4);
            int kc   = (idx % (BK / 4)) * 4;
            int grow = brow + row;
            if (grow > M - 1) grow = M - 1;
            cp_async16(&As[buf][row][kc], A + (long long)grow * K + k0 + kc);
        }
    };
    auto cpB = [&](int buf, int k0) {
        #pragma unroll
        for (int it = 0; it < BIT; it++) {
            int idx = tid + it * NT;
            int kk  = idx / (BN / 4);
            int nc  = (idx % (BN / 4)) * 4;
            cp_async16(&Bs[buf][kk][nc], Bg + (long long)(k0 + kk) * N + nc);
        }
    };
    auto compute = [&](int buf) {
        #pragma unroll
        for (int ks = 0; ks < BK / 8; ks++) {
            int kk = ks * 8;
            unsigned a[MF][4], b[NF][2];
            #pragma unroll
            for (int fm = 0; fm < MF; fm++) {
                const float* ap = &As[buf][warp_m * WM + fm * 16 + grp][kk + qi];
                a[fm][0] = f2tf32(ap[0]);
                a[fm][1] = f2tf32(ap[8 * BKp]);
                a[fm][2] = f2tf32(ap[4]);
                a[fm][3] = f2tf32(ap[8 * BKp + 4]);
            }
            #pragma unroll
            for (int fn = 0; fn < NF; fn++) {
                const float* bp = &Bs[buf][kk + qi][warp_n * WN + fn * 8 + grp];
                b[fn][0] = f2tf32(bp[0]);
                b[fn][1] = f2tf32(bp[4 * BNp]);
            }
            #pragma unroll
            for (int fm = 0; fm < MF; fm++)
                #pragma unroll
                for (int fn = 0; fn < NF; fn++)
                    mma_tf32(acc[fm][fn], a[fm], b[fn]);
        }
    };

    cpA(0, 0); cpB(0, 0); cp_commit();
    cp_wait0(); __syncthreads();

    const int KT = K / BK;
    for (int t = 1; t < KT; t++) {
        cpA(t & 1, t * BK); cpB(t & 1, t * BK); cp_commit();
        compute((t - 1) & 1);
        cp_wait0(); __syncthreads();
    }
    compute((KT - 1) & 1);

    #pragma unroll
    for (int fm = 0; fm < MF; fm++) {
        int r0 = brow + warp_m * WM + fm * 16 + grp;
        int r1 = r0 + 8;
        float d0 = 1.0f, d1 = 1.0f;
        if (SCALE_DIS) {
            d0 = (r0 < M) ? g_dis[r0] : 0.0f;
            d1 = (r1 < M) ? g_dis[r1] : 0.0f;
        }
        #pragma unroll
        for (int fn = 0; fn < NF; fn++) {
            int col = warp_n * WN + fn * 8 + 2 * qi;
            if (r0 < M)
                C[((long long)r0 * N + col) >> 1] =
                    __floats2half2_rn(acc[fm][fn][0] * d0, acc[fm][fn][1] * d0);
            if (r1 < M)
                C[((long long)r1 * N + col) >> 1] =
                    __floats2half2_rn(acc[fm][fn][2] * d1, acc[fm][fn][3] * d1);
        }
    }
}

// ───────────────────────── prep + mega (gemm1 ∥ histogram ∥ tail-zero) ─────────
__global__ void k_zero_deg() {
    int i = blockIdx.x * blockDim.x + threadIdx.x;
    if (i < NN) g_degi[i] = 0;
}

__global__ void __launch_bounds__(256)
k_mega(const float* __restrict__ x, const float* __restrict__ W1,
       const int* __restrict__ dst, int E,
       float* __restrict__ out, int SE, int total)
{
    int bx = blockIdx.x;
    if (bx < GB1) {   // gemm1: hw1h = fp16(x @ W1), unscaled
        mma_body<128, 128, 16, 64, 32, 256, false>(bx, x, W1, g_hw1h, NN, HDIM, FIN);
        return;
    }
    bx -= GB1;
    if (bx < CB) {    // degree histogram
        for (int e = bx * 256 + threadIdx.x; e < E; e += CB * 256)
            atomicAdd(&g_degi[dst[e]], 1);
        return;
    }
    bx -= CB;         // zero the tail of the output
    for (int i = SE + bx * 256 + threadIdx.x; i < total; i += ZB * 256)
        out[i] = 0.0f;
}

// ───────────────────────── CSR scan + bin ─────────────────────────
__global__ void k_scan1() {
    __shared__ int sm[256];
    int i = blockIdx.x * 256 + threadIdx.x;
    int v = (i < NN) ? g_degi[i] : 0;
    sm[threadIdx.x] = v;
    __syncthreads();
    #pragma unroll
    for (int o = 1; o < 256; o <<= 1) {
        int t = (threadIdx.x >= o) ? sm[threadIdx.x - o] : 0;
        __syncthreads();
        sm[threadIdx.x] += t;
        __syncthreads();
    }
    if (i < NN) g_rowptr[i] = sm[threadIdx.x] - v;
    if (threadIdx.x == 255) g_bsum[blockIdx.x] = sm[255];
}

__global__ void k_scan2() {
    __shared__ int sm[512];
    int v = (threadIdx.x < NB) ? g_bsum[threadIdx.x] : 0;
    sm[threadIdx.x] = v;
    __syncthreads();
    #pragma unroll
    for (int o = 1; o < 512; o <<= 1) {
        int t = (threadIdx.x >= o) ? sm[threadIdx.x - o] : 0;
        __syncthreads();
        sm[threadIdx.x] += t;
        __syncthreads();
    }
    if (threadIdx.x < NB) g_boff[threadIdx.x] = sm[threadIdx.x] - v;
}

__global__ void k_scan3(int E) {
    int i = blockIdx.x * blockDim.x + threadIdx.x;
    if (i < NN) {
        int r = g_rowptr[i] + g_boff[i >> 8];
        g_rowptr[i] = r;
        g_cursor[i] = r;
        g_dis[i]    = rsqrtf((float)g_degi[i] + 1.0f);
    }
    if (i == 0) g_rowptr[NN] = E;
}

__global__ void k_bin(const int* __restrict__ src, const int* __restrict__ dst, int E) {
    int e = blockIdx.x * blockDim.x + threadIdx.x;
    if (e >= E) return;
    int d = dst[e];
    int p = atomicAdd(&g_cursor[d], 1);
    g_esrc[p] = src[e];
}

// ───────────────────────── gather aggregation ─────────────────────────
// Layer 1: hw1h UNSCALED.  S = dv*h1[v] + Σ_e ds*h1[s];  agg1 = relu(dv*S + b1).
// 16 lanes per node, uint4 (8 halves) per lane, fp32 accumulation.
__global__ void k_gather1(const float* __restrict__ b1) {
    int t = blockIdx.x * blockDim.x + threadIdx.x;
    int v = t >> 4, lane = t & 15;
    if (v >= NN) return;
    int beg = g_rowptr[v], end = g_rowptr[v + 1];
    float dv = g_dis[v];
    const uint4* hw = (const uint4*)g_hw1h;   // 16 uint4 per row

    float a[8], a2[8], f[8];
    u4_to_f8(hw[(long long)v * 16 + lane], f);
    #pragma unroll
    for (int i = 0; i < 8; i++) { a[i] = dv * f[i]; a2[i] = 0.f; }

    int p = beg;
    for (; p + 1 < end; p += 2) {
        int sa = __ldg(&g_esrc[p]);
        int sb = __ldg(&g_esrc[p + 1]);
        float da = g_dis[sa], db = g_dis[sb];
        uint4 ua = hw[(long long)sa * 16 + lane];
        uint4 ub = hw[(long long)sb * 16 + lane];
        float fa[8], fb[8];
        u4_to_f8(ua, fa); u4_to_f8(ub, fb);
        #pragma unroll
        for (int i = 0; i < 8; i++) { a[i] += da * fa[i]; a2[i] += db * fb[i]; }
    }
    if (p < end) {
        int sa = __ldg(&g_esrc[p]);
        float da = g_dis[sa];
        float fa[8];
        u4_to_f8(hw[(long long)sa * 16 + lane], fa);
        #pragma unroll
        for (int i = 0; i < 8; i++) a[i] += da * fa[i];
    }
    float4 b0 = ((const float4*)b1)[lane * 2];
    float4 b1v = ((const float4*)b1)[lane * 2 + 1];
    float o[8];
    o[0] = fmaxf(fmaf(dv, a[0] + a2[0], b0.x), 0.f);
    o[1] = fmaxf(fmaf(dv, a[1] + a2[1], b0.y), 0.f);
    o[2] = fmaxf(fmaf(dv, a[2] + a2[2], b0.z), 0.f);
    o[3] = fmaxf(fmaf(dv, a[3] + a2[3], b0.w), 0.f);
    o[4] = fmaxf(fmaf(dv, a[4] + a2[4], b1v.x), 0.f);
    o[5] = fmaxf(fmaf(dv, a[5] + a2[5], b1v.y), 0.f);
    o[6] = fmaxf(fmaf(dv, a[6] + a2[6], b1v.z), 0.f);
    o[7] = fmaxf(fmaf(dv, a[7] + a2[7], b1v.w), 0.f);
    float4* outp = (float4*)(g_agg1 + (long long)v * HDIM + lane * 8);
    outp[0] = make_float4(o[0], o[1], o[2], o[3]);
    outp[1] = make_float4(o[4], o[5], o[6], o[7]);
}

// Layer 2: hw2h pre-scaled by dis.  acc = hw2[v] + Σ hw2[s];  agg2 = fp16(dv*acc + b2).
// 8 lanes per node, uint4 per lane.
__global__ void k_gather2(const float* __restrict__ b2) {
    int t = blockIdx.x * blockDim.x + threadIdx.x;
    int v = t >> 3, lane = t & 7;
    if (v >= NN) return;
    int beg = g_rowptr[v], end = g_rowptr[v + 1];
    float dv = g_dis[v];
    const uint4* hw = (const uint4*)g_hw2h;   // 8 uint4 per row

    float a[8], a2[8];
    u4_to_f8(hw[(long long)v * 8 + lane], a);
    #pragma unroll
    for (int i = 0; i < 8; i++) a2[i] = 0.f;

    int p = beg;
    for (; p + 1 < end; p += 2) {
        int sa = __ldg(&g_esrc[p]);
        int sb = __ldg(&g_esrc[p + 1]);
        uint4 ua = hw[(long long)sa * 8 + lane];
        uint4 ub = hw[(long long)sb * 8 + lane];
        float fa[8], fb[8];
        u4_to_f8(ua, fa); u4_to_f8(ub, fb);
        #pragma unroll
        for (int i = 0; i < 8; i++) { a[i] += fa[i]; a2[i] += fb[i]; }
    }
    if (p < end) {
        int sa = __ldg(&g_esrc[p]);
        float fa[8];
        u4_to_f8(hw[(long long)sa * 8 + lane], fa);
        #pragma unroll
        for (int i = 0; i < 8; i++) a[i] += fa[i];
    }
    float4 b0 = ((const float4*)b2)[lane * 2];
    float4 b1v = ((const float4*)b2)[lane * 2 + 1];
    float o[8];
    o[0] = fmaf(dv, a[0] + a2[0], b0.x);
    o[1] = fmaf(dv, a[1] + a2[1], b0.y);
    o[2] = fmaf(dv, a[2] + a2[2], b0.z);
    o[3] = fmaf(dv, a[3] + a2[3], b0.w);
    o[4] = fmaf(dv, a[4] + a2[4], b1v.x);
    o[5] = fmaf(dv, a[5] + a2[5], b1v.y);
    o[6] = fmaf(dv, a[6] + a2[6], b1v.z);
    o[7] = fmaf(dv, a[7] + a2[7], b1v.w);
    uint4 u;
    *(__half2*)&u.x = __floats2half2_rn(o[0], o[1]);
    *(__half2*)&u.y = __floats2half2_rn(o[2], o[3]);
    *(__half2*)&u.z = __floats2half2_rn(o[4], o[5]);
    *(__half2*)&u.w = __floats2half2_rn(o[6], o[7]);
    ((uint4*)g_agg2h)[(long long)v * 8 + lane] = u;
}

// ───────────────────────── scoring: 8 lanes/edge, uint4/lane ─────────────────────────
__global__ void k_score(const int* __restrict__ pos, const int* __restrict__ neg,
                        int EPn, int SE, float* __restrict__ out)
{
    int t = blockIdx.x * blockDim.x + threadIdx.x;
    int e = t >> 3, lane = t & 7;
    if (e >= SE) return;
    int i, j;
    if (e < EPn) { j = pos[e];       i = pos[e + EPn]; }
    else         { j = neg[e - EPn]; i = neg[e];       }
    const uint4* h4 = (const uint4*)g_agg2h;
    float fa[8], fb[8];
    u4_to_f8(h4[(long long)i * 8 + lane], fa);
    u4_to_f8(h4[(long long)j * 8 + lane], fb);
    float s = fa[0] * fb[0] + fa[1] * fb[1] + fa[2] * fb[2] + fa[3] * fb[3]
            + fa[4] * fb[4] + fa[5] * fb[5] + fa[6] * fb[6] + fa[7] * fb[7];
    #pragma unroll
    for (int o = 4; o; o >>= 1) s += __shfl_xor_sync(0xffffffffu, s, o);
    if (lane == 0) out[e] = s;
}

// ───────────────────────── gemm2 wrapper ─────────────────────────
__global__ void __launch_bounds__(256)
k_gemm2(const float* __restrict__ W2)
{
    mma_body<128, 64, 16, 32, 32, 256, true>(blockIdx.x, g_agg1, W2, g_hw2h,
                                             NN, CDIM, HDIM);
}

extern "C" void kernel_launch(void* const* d_in, const int* in_sizes, int n_in,
                              void* d_out, int out_size)
{
    const float* x   = (const float*)d_in[0];
    // d_in[1] = masked_nodes (unused by the reference output)
    const int*   pos = (const int*)d_in[2];
    const int*   neg = (const int*)d_in[3];
    const int*   ei  = (const int*)d_in[4];
    const float* W1  = (const float*)d_in[5];
    const float* b1  = (const float*)d_in[6];
    const float* W2  = (const float*)d_in[7];
    const float* b2  = (const float*)d_in[8];
    float* out = (float*)d_out;

    const int E   = in_sizes[4] / 2;
    const int EPn = in_sizes[2] / 2;
    const int SE  = 2 * EPn;
    const int* src = ei;
    const int* dst = ei + E;

    k_zero_deg<<<(NN + 255) / 256, 256>>>();

    // gemm1 ∥ degree histogram ∥ output-tail zeroing
    k_mega<<<GB1 + CB + ZB, 256>>>(x, W1, dst, E, out, SE, out_size);

    k_scan1<<<NB, 256>>>();
    k_scan2<<<1, 512>>>();
    k_scan3<<<(NN + 255) / 256, 256>>>(E);
    k_bin  <<<(E + 255) / 256, 256>>>(src, dst, E);

    k_gather1<<<(NN * 16 + 255) / 256, 256>>>(b1);

    k_gemm2<<<(NN + 127) / 128, 256>>>(W2);
    k_gather2<<<(NN * 8 + 255) / 256, 256>>>(b2);

    k_score<<<(SE * 8 + 255) / 256, 256>>>(pos, neg, EPn, SE, out);
}